// round 1
// baseline (speedup 1.0000x reference)
#include <cuda_runtime.h>

// Problem constants
static constexpr int Tn = 512;
static constexpr int Bn = 512;
static constexpr long BTn = (long)Bn * Tn;

// Scratch (device globals; allocation-free kernel_launch)
__device__ float g_xg[(size_t)512 * 512 * 288];   // max 4H = 288
__device__ float g_seqA[(size_t)512 * 512 * 64];  // e1 out / d1 out
__device__ float g_seqB[(size_t)512 * 512 * 32];  // e2 out

__device__ __forceinline__ float fsig(float x) {
    return __fdividef(1.0f, 1.0f + __expf(-x));
}
__device__ __forceinline__ float ftanh(float x) {
    return 1.0f - __fdividef(2.0f, __expf(2.0f * x) + 1.0f);
}

// ---------------------------------------------------------------------------
// Input-projection GEMM: xg[row, g] = sum_i in[row, i] * Wih[g, i] + bih[g]+bhh[g]
// row in [0, B*T). threads = G = 4H. Each thread owns gate g: Wih row in regs.
// 128 input rows staged in SMEM; reads are warp-broadcast LDS.128.
// ---------------------------------------------------------------------------
template <int IN, int G>
__global__ void __launch_bounds__(G) gemm_xg_kernel(
    const float* __restrict__ in, const float* __restrict__ Wih,
    const float* __restrict__ bih, const float* __restrict__ bhh,
    float* __restrict__ xg)
{
    constexpr int ROWS = 128;
    __shared__ __align__(16) float sIn[ROWS * IN];

    const int g = threadIdx.x;
    const size_t row0 = (size_t)blockIdx.x * ROWS;

    // Cooperative contiguous float4 copy of the 128-row input tile
    {
        const float4* src = (const float4*)(in + row0 * IN);
        float4* dst = (float4*)sIn;
        constexpr int NV = ROWS * IN / 4;
        for (int i = g; i < NV; i += G) dst[i] = src[i];
    }

    float w[IN];
#pragma unroll
    for (int i = 0; i < IN; i++) w[i] = Wih[g * IN + i];
    const float bias = bih[g] + bhh[g];

    __syncthreads();

    float* outp = xg + row0 * G + g;
#pragma unroll 1
    for (int r = 0; r < ROWS; r++) {
        float acc = bias;
        const float4* rp = (const float4*)(sIn + r * IN);
#pragma unroll
        for (int i = 0; i < IN / 4; i++) {
            float4 v = rp[i];
            acc += w[4 * i + 0] * v.x;
            acc += w[4 * i + 1] * v.y;
            acc += w[4 * i + 2] * v.z;
            acc += w[4 * i + 3] * v.w;
        }
        outp[(size_t)r * G] = acc;
    }
}

// ---------------------------------------------------------------------------
// Recurrent scan: per layer, grid = B/4 blocks, each block owns 4 batch rows
// for the full T-step scan. threads = 4H. Thread j owns gate row j of Whh
// (registers) and, in the elementwise phase, cell (r = j/H, m = j%H) with c
// in a register. h lives in SMEM (broadcast reads in the matvec).
// ---------------------------------------------------------------------------
template <int H>
__global__ void __launch_bounds__(4 * H) lstm_rec_kernel(
    const float* __restrict__ xg, const float* __restrict__ Whh,
    float* __restrict__ hout)
{
    constexpr int G4 = 4 * H;
    constexpr int R = 4;  // batch rows per block; R*H == 4H == blockDim.x
    __shared__ __align__(16) float h_sm[R * H];
    __shared__ float g_sm[R * G4];

    const int j = threadIdx.x;          // gate index 0..4H-1
    const int b0 = blockIdx.x * R;      // first batch row of this block
    const int gate = j / H;             // 0:i 1:f 2:g 3:o ; also == elementwise row r
    const int mm = j % H;

    float w[H];
#pragma unroll
    for (int k = 0; k < H; k++) w[k] = Whh[j * H + k];

    h_sm[j] = 0.0f;  // j spans exactly R*H
    float c = 0.0f;

    const float* xgp = xg + (size_t)b0 * Tn * G4 + j;
    float* hp = hout + (size_t)b0 * Tn * H + mm;

    __syncthreads();

    for (int t = 0; t < Tn; t++) {
        // gate phase: one dot per batch row r (0..3)
        float a0 = xgp[(size_t)(0 * Tn + t) * G4];
        float a1 = xgp[(size_t)(1 * Tn + t) * G4];
        float a2 = xgp[(size_t)(2 * Tn + t) * G4];
        float a3 = xgp[(size_t)(3 * Tn + t) * G4];
#pragma unroll
        for (int k = 0; k < H; k += 4) {
            const float4 h0 = *(const float4*)&h_sm[0 * H + k];
            const float4 h1 = *(const float4*)&h_sm[1 * H + k];
            const float4 h2 = *(const float4*)&h_sm[2 * H + k];
            const float4 h3 = *(const float4*)&h_sm[3 * H + k];
            a0 += w[k] * h0.x; a0 += w[k + 1] * h0.y; a0 += w[k + 2] * h0.z; a0 += w[k + 3] * h0.w;
            a1 += w[k] * h1.x; a1 += w[k + 1] * h1.y; a1 += w[k + 2] * h1.z; a1 += w[k + 3] * h1.w;
            a2 += w[k] * h2.x; a2 += w[k + 1] * h2.y; a2 += w[k + 2] * h2.z; a2 += w[k + 3] * h2.w;
            a3 += w[k] * h3.x; a3 += w[k + 1] * h3.y; a3 += w[k + 2] * h3.z; a3 += w[k + 3] * h3.w;
        }
        // activation applied by the producing thread (gate type fixed per thread)
        if (gate == 2) {
            a0 = ftanh(a0); a1 = ftanh(a1); a2 = ftanh(a2); a3 = ftanh(a3);
        } else {
            a0 = fsig(a0); a1 = fsig(a1); a2 = fsig(a2); a3 = fsig(a3);
        }
        g_sm[0 * G4 + j] = a0;
        g_sm[1 * G4 + j] = a1;
        g_sm[2 * G4 + j] = a2;
        g_sm[3 * G4 + j] = a3;
        __syncthreads();

        // elementwise phase: thread j -> (r = gate, m = mm)
        {
            const int r = gate;
            const float iv = g_sm[r * G4 + 0 * H + mm];
            const float fv = g_sm[r * G4 + 1 * H + mm];
            const float gv = g_sm[r * G4 + 2 * H + mm];
            const float ov = g_sm[r * G4 + 3 * H + mm];
            c = fv * c + iv * gv;
            const float h = ov * ftanh(c);
            h_sm[r * H + mm] = h;
            hp[(size_t)(r * Tn + t) * H] = h;
        }
        __syncthreads();
    }
}

// ---------------------------------------------------------------------------
// Launch: 4x (GEMM -> scan). Scratch ping-pongs; final scan writes d_out.
// ---------------------------------------------------------------------------
extern "C" void kernel_launch(void* const* d_in, const int* in_sizes, int n_in,
                              void* d_out, int out_size)
{
    (void)in_sizes; (void)n_in; (void)out_size;

    const float* x    = (const float*)d_in[0];
    const float* e1W  = (const float*)d_in[1];
    const float* e1U  = (const float*)d_in[2];
    const float* e1bi = (const float*)d_in[3];
    const float* e1bh = (const float*)d_in[4];
    const float* e2W  = (const float*)d_in[5];
    const float* e2U  = (const float*)d_in[6];
    const float* e2bi = (const float*)d_in[7];
    const float* e2bh = (const float*)d_in[8];
    const float* d1W  = (const float*)d_in[9];
    const float* d1U  = (const float*)d_in[10];
    const float* d1bi = (const float*)d_in[11];
    const float* d1bh = (const float*)d_in[12];
    const float* d2W  = (const float*)d_in[13];
    const float* d2U  = (const float*)d_in[14];
    const float* d2bi = (const float*)d_in[15];
    const float* d2bh = (const float*)d_in[16];
    float* out = (float*)d_out;

    float *xg = nullptr, *sa = nullptr, *sb = nullptr;
    cudaGetSymbolAddress((void**)&xg, g_xg);
    cudaGetSymbolAddress((void**)&sa, g_seqA);
    cudaGetSymbolAddress((void**)&sb, g_seqB);

    const int gemmGrid = (int)(BTn / 128);  // 2048
    const int recGrid = Bn / 4;             // 128

    // e1: 72 -> 64
    gemm_xg_kernel<72, 256><<<gemmGrid, 256>>>(x, e1W, e1bi, e1bh, xg);
    lstm_rec_kernel<64><<<recGrid, 256>>>(xg, e1U, sa);
    // e2: 64 -> 32
    gemm_xg_kernel<64, 128><<<gemmGrid, 128>>>(sa, e2W, e2bi, e2bh, xg);
    lstm_rec_kernel<32><<<recGrid, 128>>>(xg, e2U, sb);
    // d1: 32 -> 64
    gemm_xg_kernel<32, 256><<<gemmGrid, 256>>>(sb, d1W, d1bi, d1bh, xg);
    lstm_rec_kernel<64><<<recGrid, 256>>>(xg, d1U, sa);
    // d2: 64 -> 72
    gemm_xg_kernel<64, 288><<<gemmGrid, 288>>>(sa, d2W, d2bi, d2bh, xg);
    lstm_rec_kernel<72><<<recGrid, 288>>>(xg, d2U, out);
}

// round 2
// speedup vs baseline: 1.6184x; 1.6184x over previous
#include <cuda_runtime.h>

static constexpr int Tn = 512;
static constexpr int Bn = 512;
static constexpr long BTn = (long)Bn * Tn;

// Scratch (device globals; allocation-free kernel_launch)
__device__ float g_xg[(size_t)512 * 512 * 288];   // max 4H = 288
__device__ float g_seqA[(size_t)512 * 512 * 64];  // e1 out / d1 out
__device__ float g_seqB[(size_t)512 * 512 * 32];  // e2 out

__device__ __forceinline__ float fsig(float x) {
    return __fdividef(1.0f, 1.0f + __expf(-x));
}
__device__ __forceinline__ float ftanh(float x) {
    return 1.0f - __fdividef(2.0f, __expf(2.0f * x) + 1.0f);
}

// ---- packed f32x2 helpers (Blackwell) ----
__device__ __forceinline__ unsigned long long pk2(float lo, float hi) {
    unsigned long long r;
    asm("mov.b64 %0, {%1, %2};" : "=l"(r) : "f"(lo), "f"(hi));
    return r;
}
__device__ __forceinline__ void upk2(unsigned long long v, float& lo, float& hi) {
    asm("mov.b64 {%0, %1}, %2;" : "=f"(lo), "=f"(hi) : "l"(v));
}
__device__ __forceinline__ unsigned long long ffma2(
    unsigned long long a, unsigned long long b, unsigned long long c) {
    unsigned long long d;
    asm("fma.rn.f32x2 %0, %1, %2, %3;" : "=l"(d) : "l"(a), "l"(b), "l"(c));
    return d;
}

// ---------------------------------------------------------------------------
// Input-projection GEMM: xg[row, g] = sum_i in[row, i] * Wih[g, i] + bih[g]+bhh[g]
// threads = G = 4H, each thread owns one gate row of Wih (packed f32x2 regs).
// 128 input rows staged in SMEM; broadcast LDS.128 reads; 2 packed acc chains.
// ---------------------------------------------------------------------------
template <int IN, int G>
__global__ void __launch_bounds__(G, 2) gemm_xg_kernel(
    const float* __restrict__ in, const float* __restrict__ Wih,
    const float* __restrict__ bih, const float* __restrict__ bhh,
    float* __restrict__ xg)
{
    constexpr int ROWS = 128;
    __shared__ __align__(16) float sIn[ROWS * IN];

    const int g = threadIdx.x;
    const size_t row0 = (size_t)blockIdx.x * ROWS;

    {
        const float4* src = (const float4*)(in + row0 * IN);
        float4* dst = (float4*)sIn;
        constexpr int NV = ROWS * IN / 4;
        for (int i = g; i < NV; i += G) dst[i] = src[i];
    }

    unsigned long long w2[IN / 2];
    {
        const unsigned long long* wp = (const unsigned long long*)(Wih + (size_t)g * IN);
#pragma unroll
        for (int i = 0; i < IN / 2; i++) w2[i] = wp[i];
    }
    const float bias = bih[g] + bhh[g];

    __syncthreads();

    float* outp = xg + row0 * G + g;
#pragma unroll 1
    for (int r = 0; r < ROWS; r++) {
        unsigned long long accA = pk2(bias, 0.0f);
        unsigned long long accB = pk2(0.0f, 0.0f);
        const ulonglong2* rp = (const ulonglong2*)(sIn + r * IN);
#pragma unroll
        for (int i = 0; i < IN / 4; i++) {
            ulonglong2 v = rp[i];
            accA = ffma2(w2[2 * i + 0], v.x, accA);
            accB = ffma2(w2[2 * i + 1], v.y, accB);
        }
        float a0, a1, b0, b1;
        upk2(accA, a0, a1);
        upk2(accB, b0, b1);
        outp[(size_t)r * G] = (a0 + a1) + (b0 + b1);
    }
}

// ---------------------------------------------------------------------------
// Recurrent scan. Block = 4H threads, owns R batch rows for the full T scan.
// Thread j holds gate row j of Whh packed in f32x2 regs. h in SMEM (broadcast
// LDS.128). Per step: prefetch xg(t+1), R packed dot products, activation,
// gate exchange through SMEM, cell update by first R*H threads.
// ---------------------------------------------------------------------------
template <int H, int R, int MINB>
__global__ void __launch_bounds__(4 * H, MINB) lstm_rec_kernel(
    const float* __restrict__ xg, const float* __restrict__ Whh,
    float* __restrict__ hout)
{
    constexpr int G4 = 4 * H;
    __shared__ __align__(16) float h_sm[R * H];
    __shared__ float g_sm[R * G4];

    const int j = threadIdx.x;
    const int b0 = blockIdx.x * R;
    const int gate = j / H;
    const int mm = j % H;

    unsigned long long w2[H / 2];
    {
        const unsigned long long* wp = (const unsigned long long*)(Whh + (size_t)j * H);
#pragma unroll
        for (int k = 0; k < H / 2; k++) w2[k] = wp[k];
    }

    for (int i = j; i < R * H; i += G4) h_sm[i] = 0.0f;
    float c = 0.0f;

    const float* xgp = xg + (size_t)b0 * Tn * G4 + j;
    float* hp = hout + (size_t)b0 * Tn * H;

    // cell-update thread mapping (first R*H threads)
    const int cr = j / H;        // valid when j < R*H
    const int cm = j % H;

    float xn[R];
#pragma unroll
    for (int r = 0; r < R; r++) xn[r] = xgp[(size_t)r * Tn * G4];

    __syncthreads();

    for (int t = 0; t < Tn; t++) {
        unsigned long long acc[R];
#pragma unroll
        for (int r = 0; r < R; r++) acc[r] = pk2(xn[r], 0.0f);

        // prefetch next timestep's xg (consumed after 2 barriers)
        if (t + 1 < Tn) {
#pragma unroll
            for (int r = 0; r < R; r++)
                xn[r] = xgp[((size_t)r * Tn + t + 1) * G4];
        }

#pragma unroll
        for (int k = 0; k < H / 4; k++) {
#pragma unroll
            for (int r = 0; r < R; r++) {
                ulonglong2 hv = ((const ulonglong2*)&h_sm[r * H])[k];
                acc[r] = ffma2(w2[2 * k + 0], hv.x, acc[r]);
                acc[r] = ffma2(w2[2 * k + 1], hv.y, acc[r]);
            }
        }

#pragma unroll
        for (int r = 0; r < R; r++) {
            float lo, hi;
            upk2(acc[r], lo, hi);
            float a = lo + hi;
            a = (gate == 2) ? ftanh(a) : fsig(a);
            g_sm[r * G4 + j] = a;
        }
        __syncthreads();

        if (j < R * H) {
            const float iv = g_sm[cr * G4 + 0 * H + cm];
            const float fv = g_sm[cr * G4 + 1 * H + cm];
            const float gv = g_sm[cr * G4 + 2 * H + cm];
            const float ov = g_sm[cr * G4 + 3 * H + cm];
            c = fv * c + iv * gv;
            const float h = ov * ftanh(c);
            h_sm[cr * H + cm] = h;
            hp[((size_t)cr * Tn + t) * H + cm] = h;
        }
        __syncthreads();
    }
}

// ---------------------------------------------------------------------------
extern "C" void kernel_launch(void* const* d_in, const int* in_sizes, int n_in,
                              void* d_out, int out_size)
{
    (void)in_sizes; (void)n_in; (void)out_size;

    const float* x    = (const float*)d_in[0];
    const float* e1W  = (const float*)d_in[1];
    const float* e1U  = (const float*)d_in[2];
    const float* e1bi = (const float*)d_in[3];
    const float* e1bh = (const float*)d_in[4];
    const float* e2W  = (const float*)d_in[5];
    const float* e2U  = (const float*)d_in[6];
    const float* e2bi = (const float*)d_in[7];
    const float* e2bh = (const float*)d_in[8];
    const float* d1W  = (const float*)d_in[9];
    const float* d1U  = (const float*)d_in[10];
    const float* d1bi = (const float*)d_in[11];
    const float* d1bh = (const float*)d_in[12];
    const float* d2W  = (const float*)d_in[13];
    const float* d2U  = (const float*)d_in[14];
    const float* d2bi = (const float*)d_in[15];
    const float* d2bh = (const float*)d_in[16];
    float* out = (float*)d_out;

    float *xg = nullptr, *sa = nullptr, *sb = nullptr;
    cudaGetSymbolAddress((void**)&xg, g_xg);
    cudaGetSymbolAddress((void**)&sa, g_seqA);
    cudaGetSymbolAddress((void**)&sb, g_seqB);

    const int gemmGrid = (int)(BTn / 128);  // 2048

    // e1: 72 -> 64
    gemm_xg_kernel<72, 256><<<gemmGrid, 256>>>(x, e1W, e1bi, e1bh, xg);
    lstm_rec_kernel<64, 2, 2><<<Bn / 2, 256>>>(xg, e1U, sa);
    // e2: 64 -> 32
    gemm_xg_kernel<64, 128><<<gemmGrid, 128>>>(sa, e2W, e2bi, e2bh, xg);
    lstm_rec_kernel<32, 1, 4><<<Bn, 128>>>(xg, e2U, sb);
    // d1: 32 -> 64
    gemm_xg_kernel<32, 256><<<gemmGrid, 256>>>(sb, d1W, d1bi, d1bh, xg);
    lstm_rec_kernel<64, 2, 2><<<Bn / 2, 256>>>(xg, d1U, sa);
    // d2: 64 -> 72
    gemm_xg_kernel<64, 288><<<gemmGrid, 288>>>(sa, d2W, d2bi, d2bh, xg);
    lstm_rec_kernel<72, 2, 2><<<Bn / 2, 288>>>(xg, d2U, out);
}